// round 1
// baseline (speedup 1.0000x reference)
#include <cuda_runtime.h>

#define DIM   768
#define NH    12
#define HD    64
#define BATCH 8
#define SEQ   1024
#define M_TOT (BATCH * SEQ)   // 8192
#define QKV_N (3 * DIM)       // 2304

// Scratch (no allocation allowed in kernel_launch)
static __device__ float g_qkv[(size_t)M_TOT * QKV_N];   // [8192, 2304]
static __device__ float g_attn[(size_t)M_TOT * DIM];    // [8192, 768]

// ---------------------------------------------------------------------------
// C[M,N] = A[M,K] @ W[N,K]^T + bias[N]
// 128x128 tile, BK=8, 256 threads, 8x8 per thread.
// Requires M%128==0, N%128==0, K%8==0 (true for all our shapes).
// ---------------------------------------------------------------------------
__global__ __launch_bounds__(256) void sgemm_bias(
    const float* __restrict__ A, const float* __restrict__ W,
    const float* __restrict__ bias, float* __restrict__ C,
    int M, int N, int K)
{
    __shared__ float As[8][128];
    __shared__ float Ws[8][128];

    const int tid = threadIdx.x;
    const int bm  = blockIdx.y * 128;
    const int bn  = blockIdx.x * 128;
    const int tr  = (tid / 16) * 8;   // row offset in tile
    const int tc  = (tid % 16) * 8;   // col offset in tile
    const int lr  = tid >> 1;         // 0..127 load row
    const int lc  = (tid & 1) * 4;    // 0 or 4 load col (float4)

    const float* Aptr = A + (size_t)(bm + lr) * K + lc;
    const float* Wptr = W + (size_t)(bn + lr) * K + lc;

    float acc[8][8];
#pragma unroll
    for (int i = 0; i < 8; i++)
#pragma unroll
        for (int j = 0; j < 8; j++) acc[i][j] = 0.f;

    for (int k0 = 0; k0 < K; k0 += 8) {
        float4 av = *(const float4*)(Aptr + k0);
        float4 wv = *(const float4*)(Wptr + k0);
        As[lc + 0][lr] = av.x; As[lc + 1][lr] = av.y;
        As[lc + 2][lr] = av.z; As[lc + 3][lr] = av.w;
        Ws[lc + 0][lr] = wv.x; Ws[lc + 1][lr] = wv.y;
        Ws[lc + 2][lr] = wv.z; Ws[lc + 3][lr] = wv.w;
        __syncthreads();

#pragma unroll
        for (int k = 0; k < 8; k++) {
            float4 a0 = *(const float4*)&As[k][tr];
            float4 a1 = *(const float4*)&As[k][tr + 4];
            float4 b0 = *(const float4*)&Ws[k][tc];
            float4 b1 = *(const float4*)&Ws[k][tc + 4];
            float ra[8] = {a0.x, a0.y, a0.z, a0.w, a1.x, a1.y, a1.z, a1.w};
            float rb[8] = {b0.x, b0.y, b0.z, b0.w, b1.x, b1.y, b1.z, b1.w};
#pragma unroll
            for (int i = 0; i < 8; i++)
#pragma unroll
                for (int j = 0; j < 8; j++)
                    acc[i][j] += ra[i] * rb[j];
        }
        __syncthreads();
    }

    float bb[8];
#pragma unroll
    for (int j = 0; j < 8; j++) bb[j] = bias[bn + tc + j];

#pragma unroll
    for (int i = 0; i < 8; i++) {
        float* crow = C + (size_t)(bm + tr + i) * N + bn + tc;
        float4 c0, c1;
        c0.x = acc[i][0] + bb[0]; c0.y = acc[i][1] + bb[1];
        c0.z = acc[i][2] + bb[2]; c0.w = acc[i][3] + bb[3];
        c1.x = acc[i][4] + bb[4]; c1.y = acc[i][5] + bb[5];
        c1.z = acc[i][6] + bb[6]; c1.w = acc[i][7] + bb[7];
        *(float4*)(crow + 0) = c0;
        *(float4*)(crow + 4) = c1;
    }
}

// ---------------------------------------------------------------------------
// Flash attention over g_qkv: layout per row (token) is [3*768]:
//   q = [0 + h*64 .. ), k = [768 + h*64 .. ), v = [1536 + h*64 .. )
// grid = (SEQ/64, BATCH*NH), 256 threads.
// Each block: 64 query rows; per thread: 1 query row (4 threads/row),
// 8 score cols per key-tile of 32, 16 output dims.
// ---------------------------------------------------------------------------
__global__ __launch_bounds__(256) void attn_kernel(const float* __restrict__ qkv,
                                                   float* __restrict__ out)
{
    __shared__ float Qs[64][68];
    __shared__ float Ks[32][68];
    __shared__ float Vs[32][68];
    __shared__ float Ps[64][36];

    const int tid = threadIdx.x;
    const int qt  = blockIdx.x * 64;
    const int bh  = blockIdx.y;
    const int b   = bh / NH;
    const int h   = bh % NH;
    const float SCALE = 0.125f;  // 64^-0.5

    const float* base = qkv + (size_t)b * SEQ * QKV_N + h * HD;

    // Load Q tile (scaled)
    for (int i = tid; i < 64 * 16; i += 256) {
        int r = i >> 4, c = (i & 15) << 2;
        float4 v = *(const float4*)&base[(size_t)(qt + r) * QKV_N + c];
        Qs[r][c + 0] = v.x * SCALE; Qs[r][c + 1] = v.y * SCALE;
        Qs[r][c + 2] = v.z * SCALE; Qs[r][c + 3] = v.w * SCALE;
    }

    const int r  = tid >> 2;          // query row 0..63
    const int kc = (tid & 3) * 8;     // key col base within 32-tile
    const int db = (tid & 3) * 16;    // output dim base

    float o[16];
#pragma unroll
    for (int j = 0; j < 16; j++) o[j] = 0.f;
    float mrow = -1e30f, lrow = 0.f;

    for (int kt = 0; kt < SEQ / 32; kt++) {
        __syncthreads();  // previous iter's Vs/Ps readers done; Q load done (iter 0)

        // Load K and V tiles (32 x 64)
        for (int i = tid; i < 32 * 16; i += 256) {
            int rr = i >> 4, c = (i & 15) << 2;
            const float* kp = &base[(size_t)(kt * 32 + rr) * QKV_N + DIM + c];
            float4 kv = *(const float4*)kp;
            float4 vv = *(const float4*)(kp + DIM);
            Ks[rr][c + 0] = kv.x; Ks[rr][c + 1] = kv.y;
            Ks[rr][c + 2] = kv.z; Ks[rr][c + 3] = kv.w;
            Vs[rr][c + 0] = vv.x; Vs[rr][c + 1] = vv.y;
            Vs[rr][c + 2] = vv.z; Vs[rr][c + 3] = vv.w;
        }
        __syncthreads();

        // S = Q @ K^T   (8 keys per thread)
        float s[8];
#pragma unroll
        for (int j = 0; j < 8; j++) s[j] = 0.f;
        const float4* q4 = (const float4*)&Qs[r][0];
#pragma unroll
        for (int d4 = 0; d4 < 16; d4++) {
            float4 q = q4[d4];
#pragma unroll
            for (int j = 0; j < 8; j++) {
                float4 k4 = *(const float4*)&Ks[kc + j][d4 * 4];
                s[j] += q.x * k4.x + q.y * k4.y + q.z * k4.z + q.w * k4.w;
            }
        }

        // Online softmax (row shared by 4 consecutive lanes)
        float mt = s[0];
#pragma unroll
        for (int j = 1; j < 8; j++) mt = fmaxf(mt, s[j]);
        mt = fmaxf(mt, __shfl_xor_sync(0xffffffffu, mt, 1));
        mt = fmaxf(mt, __shfl_xor_sync(0xffffffffu, mt, 2));
        float mnew  = fmaxf(mrow, mt);
        float alpha = __expf(mrow - mnew);
        float ls = 0.f;
#pragma unroll
        for (int j = 0; j < 8; j++) { s[j] = __expf(s[j] - mnew); ls += s[j]; }
        ls += __shfl_xor_sync(0xffffffffu, ls, 1);
        ls += __shfl_xor_sync(0xffffffffu, ls, 2);
        lrow = lrow * alpha + ls;
        mrow = mnew;

#pragma unroll
        for (int j = 0; j < 16; j++) o[j] *= alpha;
#pragma unroll
        for (int j = 0; j < 8; j++) Ps[r][kc + j] = s[j];
        __syncthreads();

        // O += P @ V   (16 output dims per thread)
#pragma unroll
        for (int c = 0; c < 32; c++) {
            float p = Ps[r][c];
            const float4* v4 = (const float4*)&Vs[c][db];
#pragma unroll
            for (int j4 = 0; j4 < 4; j4++) {
                float4 v = v4[j4];
                o[j4 * 4 + 0] += p * v.x;
                o[j4 * 4 + 1] += p * v.y;
                o[j4 * 4 + 2] += p * v.z;
                o[j4 * 4 + 3] += p * v.w;
            }
        }
    }

    // Write O / l  -> [B, T, H*hd]
    float inv = 1.f / lrow;
    float* op = out + (size_t)b * SEQ * DIM + (size_t)(qt + r) * DIM + h * HD + db;
#pragma unroll
    for (int j4 = 0; j4 < 4; j4++) {
        float4 v;
        v.x = o[j4 * 4 + 0] * inv; v.y = o[j4 * 4 + 1] * inv;
        v.z = o[j4 * 4 + 2] * inv; v.w = o[j4 * 4 + 3] * inv;
        *(float4*)(op + j4 * 4) = v;
    }
}

extern "C" void kernel_launch(void* const* d_in, const int* in_sizes, int n_in,
                              void* d_out, int out_size)
{
    const float* x      = (const float*)d_in[0];
    const float* qkv_w  = (const float*)d_in[1];
    const float* qkv_b  = (const float*)d_in[2];
    const float* proj_w = (const float*)d_in[3];
    const float* proj_b = (const float*)d_in[4];
    float* out = (float*)d_out;

    float* qkv;
    float* attn;
    cudaGetSymbolAddress((void**)&qkv,  g_qkv);
    cudaGetSymbolAddress((void**)&attn, g_attn);

    // QKV projection: [8192, 2304]
    sgemm_bias<<<dim3(QKV_N / 128, M_TOT / 128), 256>>>(
        x, qkv_w, qkv_b, qkv, M_TOT, QKV_N, DIM);

    // Attention: [8192, 768]
    attn_kernel<<<dim3(SEQ / 64, BATCH * NH), 256>>>(qkv, attn);

    // Output projection: [8192, 768]
    sgemm_bias<<<dim3(DIM / 128, M_TOT / 128), 256>>>(
        attn, proj_w, proj_b, out, M_TOT, DIM, DIM);
}

// round 2
// speedup vs baseline: 3.0569x; 3.0569x over previous
#include <cuda_runtime.h>

#define DIM   768
#define NH    12
#define HD    64
#define BATCH 8
#define SEQ   1024
#define M_TOT (BATCH * SEQ)   // 8192
#define QKV_N (3 * DIM)       // 2304

#define BR 128
#define BC 64
#define SSTR 68               // smem row stride (floats), 16B aligned

// Scratch (no allocation allowed in kernel_launch)
static __device__ float g_qkv[(size_t)M_TOT * QKV_N];   // [8192, 2304]
static __device__ float g_attn[(size_t)M_TOT * DIM];    // [8192, 768]

// ---------------------------------------------------------------------------
// C[M,N] = A[M,K] @ W[N,K]^T + bias[N]  (unchanged from round 1)
// ---------------------------------------------------------------------------
__global__ __launch_bounds__(256) void sgemm_bias(
    const float* __restrict__ A, const float* __restrict__ W,
    const float* __restrict__ bias, float* __restrict__ C,
    int M, int N, int K)
{
    __shared__ float As[8][128];
    __shared__ float Ws[8][128];

    const int tid = threadIdx.x;
    const int bm  = blockIdx.y * 128;
    const int bn  = blockIdx.x * 128;
    const int tr  = (tid / 16) * 8;
    const int tc  = (tid % 16) * 8;
    const int lr  = tid >> 1;
    const int lc  = (tid & 1) * 4;

    const float* Aptr = A + (size_t)(bm + lr) * K + lc;
    const float* Wptr = W + (size_t)(bn + lr) * K + lc;

    float acc[8][8];
#pragma unroll
    for (int i = 0; i < 8; i++)
#pragma unroll
        for (int j = 0; j < 8; j++) acc[i][j] = 0.f;

    for (int k0 = 0; k0 < K; k0 += 8) {
        float4 av = *(const float4*)(Aptr + k0);
        float4 wv = *(const float4*)(Wptr + k0);
        As[lc + 0][lr] = av.x; As[lc + 1][lr] = av.y;
        As[lc + 2][lr] = av.z; As[lc + 3][lr] = av.w;
        Ws[lc + 0][lr] = wv.x; Ws[lc + 1][lr] = wv.y;
        Ws[lc + 2][lr] = wv.z; Ws[lc + 3][lr] = wv.w;
        __syncthreads();

#pragma unroll
        for (int k = 0; k < 8; k++) {
            float4 a0 = *(const float4*)&As[k][tr];
            float4 a1 = *(const float4*)&As[k][tr + 4];
            float4 b0 = *(const float4*)&Ws[k][tc];
            float4 b1 = *(const float4*)&Ws[k][tc + 4];
            float ra[8] = {a0.x, a0.y, a0.z, a0.w, a1.x, a1.y, a1.z, a1.w};
            float rb[8] = {b0.x, b0.y, b0.z, b0.w, b1.x, b1.y, b1.z, b1.w};
#pragma unroll
            for (int i = 0; i < 8; i++)
#pragma unroll
                for (int j = 0; j < 8; j++)
                    acc[i][j] += ra[i] * rb[j];
        }
        __syncthreads();
    }

    float bb[8];
#pragma unroll
    for (int j = 0; j < 8; j++) bb[j] = bias[bn + tc + j];

#pragma unroll
    for (int i = 0; i < 8; i++) {
        float* crow = C + (size_t)(bm + tr + i) * N + bn + tc;
        float4 c0, c1;
        c0.x = acc[i][0] + bb[0]; c0.y = acc[i][1] + bb[1];
        c0.z = acc[i][2] + bb[2]; c0.w = acc[i][3] + bb[3];
        c1.x = acc[i][4] + bb[4]; c1.y = acc[i][5] + bb[5];
        c1.z = acc[i][6] + bb[6]; c1.w = acc[i][7] + bb[7];
        *(float4*)(crow + 0) = c0;
        *(float4*)(crow + 4) = c1;
    }
}

// ---------------------------------------------------------------------------
// Flash attention, register-blocked. Br=128 queries, Bc=64 keys, 256 threads.
// Thread (trow, tcol) with trow=tid/16, tcol=tid%16:
//   owns S rows trow*8..+7, S cols {tcol + 16j, j=0..3} (strided -> 2-way LDS
//   conflicts max on K), O dims tcol*4..+3.
// Row softmax reduced across the 16 tcol lanes via shfl (same half-warp).
// ---------------------------------------------------------------------------
__global__ __launch_bounds__(256) void attn_kernel(const float* __restrict__ qkv,
                                                   float* __restrict__ out)
{
    extern __shared__ float sm[];
    float* Qs = sm;                      // [BR][SSTR]
    float* Ks = Qs + BR * SSTR;          // [BC][SSTR]
    float* Vs = Ks + BC * SSTR;          // [BC][SSTR]
    float* Ps = Vs + BC * SSTR;          // [BR][SSTR]

    const int tid  = threadIdx.x;
    const int tcol = tid & 15;
    const int trow = tid >> 4;
    const int r0   = trow * 8;
    const int d0   = tcol * 4;
    const int qt   = blockIdx.x * BR;
    const int b    = blockIdx.y / NH;
    const int h    = blockIdx.y % NH;
    const float SCALE = 0.125f;

    const float* base = qkv + (size_t)b * SEQ * QKV_N + h * HD;

    // Load Q tile (scaled): 128 x 64
    for (int i = tid; i < BR * 16; i += 256) {
        int r = i >> 4, c = (i & 15) << 2;
        float4 v = *(const float4*)&base[(size_t)(qt + r) * QKV_N + c];
        float* q = &Qs[r * SSTR + c];
        q[0] = v.x * SCALE; q[1] = v.y * SCALE;
        q[2] = v.z * SCALE; q[3] = v.w * SCALE;
    }

    float o[8][4];
    float m[8], l[8];
#pragma unroll
    for (int i = 0; i < 8; i++) {
        m[i] = -1e30f; l[i] = 0.f;
#pragma unroll
        for (int j = 0; j < 4; j++) o[i][j] = 0.f;
    }

    for (int kt = 0; kt < SEQ / BC; kt++) {
        __syncthreads();  // prior PV readers done; Q store visible (kt=0)

        // Load K,V tiles: 64 x 64 each
        for (int i = tid; i < BC * 16; i += 256) {
            int rr = i >> 4, c = (i & 15) << 2;
            const float* kp = &base[(size_t)(kt * BC + rr) * QKV_N + DIM + c];
            float4 kv = *(const float4*)kp;
            float4 vv = *(const float4*)(kp + DIM);
            float* ks = &Ks[rr * SSTR + c];
            float* vs = &Vs[rr * SSTR + c];
            ks[0] = kv.x; ks[1] = kv.y; ks[2] = kv.z; ks[3] = kv.w;
            vs[0] = vv.x; vs[1] = vv.y; vs[2] = vv.z; vs[3] = vv.w;
        }
        __syncthreads();

        // S = Q @ K^T : 8 rows x 4 strided cols per thread
        float s[8][4];
#pragma unroll
        for (int i = 0; i < 8; i++)
#pragma unroll
            for (int j = 0; j < 4; j++) s[i][j] = 0.f;

#pragma unroll 2
        for (int d4 = 0; d4 < 16; d4++) {
            float4 kk[4];
#pragma unroll
            for (int j = 0; j < 4; j++)
                kk[j] = *(const float4*)&Ks[(tcol + 16 * j) * SSTR + d4 * 4];
#pragma unroll
            for (int i = 0; i < 8; i++) {
                float4 q = *(const float4*)&Qs[(r0 + i) * SSTR + d4 * 4];
#pragma unroll
                for (int j = 0; j < 4; j++)
                    s[i][j] += q.x * kk[j].x + q.y * kk[j].y +
                               q.z * kk[j].z + q.w * kk[j].w;
            }
        }

        // Online softmax per row (reduce across 16 tcol lanes)
#pragma unroll
        for (int i = 0; i < 8; i++) {
            float mt = fmaxf(fmaxf(s[i][0], s[i][1]), fmaxf(s[i][2], s[i][3]));
            mt = fmaxf(mt, __shfl_xor_sync(0xffffffffu, mt, 1));
            mt = fmaxf(mt, __shfl_xor_sync(0xffffffffu, mt, 2));
            mt = fmaxf(mt, __shfl_xor_sync(0xffffffffu, mt, 4));
            mt = fmaxf(mt, __shfl_xor_sync(0xffffffffu, mt, 8));
            float mnew  = fmaxf(m[i], mt);
            float alpha = __expf(m[i] - mnew);
            float ls = 0.f;
#pragma unroll
            for (int j = 0; j < 4; j++) {
                s[i][j] = __expf(s[i][j] - mnew);
                ls += s[i][j];
            }
            ls += __shfl_xor_sync(0xffffffffu, ls, 1);
            ls += __shfl_xor_sync(0xffffffffu, ls, 2);
            ls += __shfl_xor_sync(0xffffffffu, ls, 4);
            ls += __shfl_xor_sync(0xffffffffu, ls, 8);
            l[i] = l[i] * alpha + ls;
            m[i] = mnew;
#pragma unroll
            for (int j = 0; j < 4; j++) o[i][j] *= alpha;
            // store P (strided cols)
            float* pr = &Ps[(r0 + i) * SSTR + tcol];
#pragma unroll
            for (int j = 0; j < 4; j++) pr[16 * j] = s[i][j];
        }
        __syncthreads();

        // O += P @ V : contraction over 64 keys
#pragma unroll 2
        for (int c4 = 0; c4 < 16; c4++) {
            float4 vv[4];
#pragma unroll
            for (int j = 0; j < 4; j++)
                vv[j] = *(const float4*)&Vs[(c4 * 4 + j) * SSTR + d0];
#pragma unroll
            for (int i = 0; i < 8; i++) {
                float4 p = *(const float4*)&Ps[(r0 + i) * SSTR + c4 * 4];
                o[i][0] += p.x * vv[0].x + p.y * vv[1].x + p.z * vv[2].x + p.w * vv[3].x;
                o[i][1] += p.x * vv[0].y + p.y * vv[1].y + p.z * vv[2].y + p.w * vv[3].y;
                o[i][2] += p.x * vv[0].z + p.y * vv[1].z + p.z * vv[2].z + p.w * vv[3].z;
                o[i][3] += p.x * vv[0].w + p.y * vv[1].w + p.z * vv[2].w + p.w * vv[3].w;
            }
        }
    }

    // Write O / l -> [B, T, H*hd]
#pragma unroll
    for (int i = 0; i < 8; i++) {
        float inv = 1.f / l[i];
        float4 v;
        v.x = o[i][0] * inv; v.y = o[i][1] * inv;
        v.z = o[i][2] * inv; v.w = o[i][3] * inv;
        float* op = out + (size_t)b * SEQ * DIM + (size_t)(qt + r0 + i) * DIM
                  + h * HD + d0;
        *(float4*)op = v;
    }
}

extern "C" void kernel_launch(void* const* d_in, const int* in_sizes, int n_in,
                              void* d_out, int out_size)
{
    const float* x      = (const float*)d_in[0];
    const float* qkv_w  = (const float*)d_in[1];
    const float* qkv_b  = (const float*)d_in[2];
    const float* proj_w = (const float*)d_in[3];
    const float* proj_b = (const float*)d_in[4];
    float* out = (float*)d_out;

    float* qkv;
    float* attn;
    cudaGetSymbolAddress((void**)&qkv,  g_qkv);
    cudaGetSymbolAddress((void**)&attn, g_attn);

    const int attn_smem = SSTR * (BR + BC + BC + BR) * sizeof(float); // 104448
    cudaFuncSetAttribute(attn_kernel,
                         cudaFuncAttributeMaxDynamicSharedMemorySize, attn_smem);

    // QKV projection: [8192, 2304]
    sgemm_bias<<<dim3(QKV_N / 128, M_TOT / 128), 256>>>(
        x, qkv_w, qkv_b, qkv, M_TOT, QKV_N, DIM);

    // Attention: [8192, 768]
    attn_kernel<<<dim3(SEQ / BR, BATCH * NH), 256, attn_smem>>>(qkv, attn);

    // Output projection: [8192, 768]
    sgemm_bias<<<dim3(DIM / 128, M_TOT / 128), 256>>>(
        attn, proj_w, proj_b, out, M_TOT, DIM, DIM);
}

// round 4
// speedup vs baseline: 4.6672x; 1.5268x over previous
#include <cuda_runtime.h>
#include <cuda_bf16.h>
#include <cstdint>

#define DIM   768
#define NH    12
#define HD    64
#define BATCH 8
#define SEQ   1024
#define M_TOT (BATCH * SEQ)   // 8192
#define QKV_N (3 * DIM)       // 2304

#define BR 128
#define BC 64
#define SSTR 68

// Scratch (no allocation allowed in kernel_launch)
static __device__ float g_qkv[(size_t)M_TOT * QKV_N];          // [8192, 2304] f32
static __device__ __nv_bfloat16 g_xh[(size_t)M_TOT * DIM];     // x hi/lo
static __device__ __nv_bfloat16 g_xl[(size_t)M_TOT * DIM];
static __device__ __nv_bfloat16 g_qwh[(size_t)QKV_N * DIM];    // qkv_w hi/lo
static __device__ __nv_bfloat16 g_qwl[(size_t)QKV_N * DIM];
static __device__ __nv_bfloat16 g_pwh[(size_t)DIM * DIM];      // proj_w hi/lo
static __device__ __nv_bfloat16 g_pwl[(size_t)DIM * DIM];
static __device__ __nv_bfloat16 g_ah[(size_t)M_TOT * DIM];     // attn out hi/lo
static __device__ __nv_bfloat16 g_al[(size_t)M_TOT * DIM];

// ---------------------------------------------------------------------------
// helpers
// ---------------------------------------------------------------------------
__device__ __forceinline__ uint32_t smem_u32(const void* p) {
    uint32_t a;
    asm("{ .reg .u64 t; cvta.to.shared.u64 t, %1; cvt.u32.u64 %0, t; }"
        : "=r"(a) : "l"(p));
    return a;
}
__device__ __forceinline__ void split1(float v, __nv_bfloat16& h, __nv_bfloat16& l) {
    h = __float2bfloat16(v);
    l = __float2bfloat16(v - __bfloat162float(h));
}
__device__ __forceinline__ uint32_t pack2(__nv_bfloat16 a, __nv_bfloat16 b) {
    return (uint32_t)__bfloat16_as_ushort(a) |
           ((uint32_t)__bfloat16_as_ushort(b) << 16);
}

#define LDX4(r, addr)                                                        \
    asm volatile("ldmatrix.sync.aligned.m8n8.x4.shared.b16 {%0,%1,%2,%3}, [%4];" \
        : "=r"((r)[0]), "=r"((r)[1]), "=r"((r)[2]), "=r"((r)[3])             \
        : "r"(addr))

#define MMA_BF16(c, a, b0, b1)                                               \
    asm volatile("mma.sync.aligned.m16n8k16.row.col.f32.bf16.bf16.f32 "      \
        "{%0,%1,%2,%3},{%4,%5,%6,%7},{%8,%9},{%0,%1,%2,%3};"                 \
        : "+f"((c)[0]), "+f"((c)[1]), "+f"((c)[2]), "+f"((c)[3])             \
        : "r"((a)[0]), "r"((a)[1]), "r"((a)[2]), "r"((a)[3]),                \
          "r"(b0), "r"(b1))

// ---------------------------------------------------------------------------
// f32 -> (hi, lo) bf16 split, vectorized by 4
// ---------------------------------------------------------------------------
__global__ void split_kernel(const float* __restrict__ in,
                             __nv_bfloat16* __restrict__ h,
                             __nv_bfloat16* __restrict__ l, int n)
{
    int i = (blockIdx.x * blockDim.x + threadIdx.x) * 4;
    if (i >= n) return;
    float4 v = *(const float4*)(in + i);
    __nv_bfloat16 h0, h1, h2, h3, l0, l1, l2, l3;
    split1(v.x, h0, l0); split1(v.y, h1, l1);
    split1(v.z, h2, l2); split1(v.w, h3, l3);
    uint2 hv, lv;
    hv.x = pack2(h0, h1); hv.y = pack2(h2, h3);
    lv.x = pack2(l0, l1); lv.y = pack2(l2, l3);
    *(uint2*)(h + i) = hv;
    *(uint2*)(l + i) = lv;
}

// ---------------------------------------------------------------------------
// bf16 3-term GEMM: C[M,N] = A[M,K] @ W[N,K]^T + bias
// A,W given as hi/lo bf16. 128x128 CTA tile, BK=32, 256 threads.
// Warp w: wm = w&1 -> rows wm*64.., wn = w>>1 -> cols wn*32..
// smem row stride 40 bf16 (80B) -> conflict-free ldmatrix.
// ---------------------------------------------------------------------------
#define SB 40

__global__ __launch_bounds__(256) void gemm_bf16x3(
    const __nv_bfloat16* __restrict__ Ah, const __nv_bfloat16* __restrict__ Al,
    const __nv_bfloat16* __restrict__ Bh, const __nv_bfloat16* __restrict__ Bl,
    const float* __restrict__ bias, float* __restrict__ C, int N, int K)
{
    __shared__ __align__(16) __nv_bfloat16 sAh[128 * SB];
    __shared__ __align__(16) __nv_bfloat16 sAl[128 * SB];
    __shared__ __align__(16) __nv_bfloat16 sBh[128 * SB];
    __shared__ __align__(16) __nv_bfloat16 sBl[128 * SB];

    const int tid  = threadIdx.x;
    const int wid  = tid >> 5;
    const int lane = tid & 31;
    const int wm   = wid & 1;       // 0,1  -> 64-row halves
    const int wn   = wid >> 1;      // 0..3 -> 32-col quarters
    const int bm   = blockIdx.y * 128;
    const int bn   = blockIdx.x * 128;

    const uint32_t uAh = smem_u32(sAh), uAl = smem_u32(sAl);
    const uint32_t uBh = smem_u32(sBh), uBl = smem_u32(sBl);

    // ldmatrix per-lane offsets (bytes)
    const uint32_t offA = (uint32_t)(lane & 15) * (SB * 2) + ((lane & 16) ? 16 : 0);
    const uint32_t offB = (uint32_t)(((lane & 16) >> 1) + (lane & 7)) * (SB * 2)
                        + ((lane & 8) ? 16 : 0);

    // gmem loader mapping: row = tid/2 (0..127), col half cb = (tid&1)*16
    const int lrow = tid >> 1;
    const int cb   = (tid & 1) * 16;
    const __nv_bfloat16* pAh = Ah + (size_t)(bm + lrow) * K + cb;
    const __nv_bfloat16* pAl = Al + (size_t)(bm + lrow) * K + cb;
    const __nv_bfloat16* pBh = Bh + (size_t)(bn + lrow) * K + cb;
    const __nv_bfloat16* pBl = Bl + (size_t)(bn + lrow) * K + cb;
    __nv_bfloat16* qAh = &sAh[lrow * SB + cb];
    __nv_bfloat16* qAl = &sAl[lrow * SB + cb];
    __nv_bfloat16* qBh = &sBh[lrow * SB + cb];
    __nv_bfloat16* qBl = &sBl[lrow * SB + cb];

    float acc[4][4][4];
#pragma unroll
    for (int t = 0; t < 4; t++)
#pragma unroll
        for (int u = 0; u < 4; u++)
#pragma unroll
            for (int j = 0; j < 4; j++) acc[t][u][j] = 0.f;

    const int nit = K / 32;
    uint4 rah0 = *(const uint4*)(pAh);     uint4 rah1 = *(const uint4*)(pAh + 8);
    uint4 ral0 = *(const uint4*)(pAl);     uint4 ral1 = *(const uint4*)(pAl + 8);
    uint4 rbh0 = *(const uint4*)(pBh);     uint4 rbh1 = *(const uint4*)(pBh + 8);
    uint4 rbl0 = *(const uint4*)(pBl);     uint4 rbl1 = *(const uint4*)(pBl + 8);

    for (int c = 0; c < nit; c++) {
        *(uint4*)(qAh) = rah0; *(uint4*)(qAh + 8) = rah1;
        *(uint4*)(qAl) = ral0; *(uint4*)(qAl + 8) = ral1;
        *(uint4*)(qBh) = rbh0; *(uint4*)(qBh + 8) = rbh1;
        *(uint4*)(qBl) = rbl0; *(uint4*)(qBl + 8) = rbl1;
        __syncthreads();

        if (c + 1 < nit) {
            const int k0 = (c + 1) * 32;
            rah0 = *(const uint4*)(pAh + k0); rah1 = *(const uint4*)(pAh + k0 + 8);
            ral0 = *(const uint4*)(pAl + k0); ral1 = *(const uint4*)(pAl + k0 + 8);
            rbh0 = *(const uint4*)(pBh + k0); rbh1 = *(const uint4*)(pBh + k0 + 8);
            rbl0 = *(const uint4*)(pBl + k0); rbl1 = *(const uint4*)(pBl + k0 + 8);
        }

#pragma unroll
        for (int kk = 0; kk < 32; kk += 16) {
            uint32_t ah[4][4], al[4][4], bh[2][4], bl[2][4];
#pragma unroll
            for (int t = 0; t < 4; t++) {
                uint32_t base = (uint32_t)((wm * 64 + t * 16) * (SB * 2)) + kk * 2;
                LDX4(ah[t], uAh + base + offA);
                LDX4(al[t], uAl + base + offA);
            }
#pragma unroll
            for (int p = 0; p < 2; p++) {
                uint32_t base = (uint32_t)((wn * 32 + p * 16) * (SB * 2)) + kk * 2;
                LDX4(bh[p], uBh + base + offB);
                LDX4(bl[p], uBl + base + offB);
            }
#pragma unroll
            for (int t = 0; t < 4; t++) {
#pragma unroll
                for (int u = 0; u < 4; u++) {
                    const int p = u >> 1, o = (u & 1) * 2;
                    MMA_BF16(acc[t][u], ah[t], bh[p][o], bh[p][o + 1]);
                    MMA_BF16(acc[t][u], ah[t], bl[p][o], bl[p][o + 1]);
                    MMA_BF16(acc[t][u], al[t], bh[p][o], bh[p][o + 1]);
                }
            }
        }
        __syncthreads();
    }

    // Epilogue: lane j of mma tile: rows j/4 (+8), cols (j%4)*2 (+1)
    const int er = lane >> 2;
    const int ec = (lane & 3) * 2;
#pragma unroll
    for (int t = 0; t < 4; t++) {
        const int row = bm + wm * 64 + t * 16 + er;
#pragma unroll
        for (int u = 0; u < 4; u++) {
            const int col = bn + wn * 32 + u * 8 + ec;
            const float b0 = bias[col], b1 = bias[col + 1];
            float2 v0 = {acc[t][u][0] + b0, acc[t][u][1] + b1};
            float2 v1 = {acc[t][u][2] + b0, acc[t][u][3] + b1};
            *(float2*)&C[(size_t)row * N + col]       = v0;
            *(float2*)&C[(size_t)(row + 8) * N + col] = v1;
        }
    }
}

// ---------------------------------------------------------------------------
// Flash attention (round-2 compute), epilogue emits bf16 hi/lo for proj GEMM
// ---------------------------------------------------------------------------
__global__ __launch_bounds__(256) void attn_kernel(const float* __restrict__ qkv,
                                                   __nv_bfloat16* __restrict__ oh,
                                                   __nv_bfloat16* __restrict__ ol)
{
    extern __shared__ float sm[];
    float* Qs = sm;
    float* Ks = Qs + BR * SSTR;
    float* Vs = Ks + BC * SSTR;
    float* Ps = Vs + BC * SSTR;

    const int tid  = threadIdx.x;
    const int tcol = tid & 15;
    const int trow = tid >> 4;
    const int r0   = trow * 8;
    const int d0   = tcol * 4;
    const int qt   = blockIdx.x * BR;
    const int b    = blockIdx.y / NH;
    const int h    = blockIdx.y % NH;
    const float SCALE = 0.125f;

    const float* base = qkv + (size_t)b * SEQ * QKV_N + h * HD;

    for (int i = tid; i < BR * 16; i += 256) {
        int r = i >> 4, c = (i & 15) << 2;
        float4 v = *(const float4*)&base[(size_t)(qt + r) * QKV_N + c];
        float* q = &Qs[r * SSTR + c];
        q[0] = v.x * SCALE; q[1] = v.y * SCALE;
        q[2] = v.z * SCALE; q[3] = v.w * SCALE;
    }

    float o[8][4];
    float m[8], l[8];
#pragma unroll
    for (int i = 0; i < 8; i++) {
        m[i] = -1e30f; l[i] = 0.f;
#pragma unroll
        for (int j = 0; j < 4; j++) o[i][j] = 0.f;
    }

    for (int kt = 0; kt < SEQ / BC; kt++) {
        __syncthreads();

        for (int i = tid; i < BC * 16; i += 256) {
            int rr = i >> 4, c = (i & 15) << 2;
            const float* kp = &base[(size_t)(kt * BC + rr) * QKV_N + DIM + c];
            float4 kv = *(const float4*)kp;
            float4 vv = *(const float4*)(kp + DIM);
            float* ks = &Ks[rr * SSTR + c];
            float* vs = &Vs[rr * SSTR + c];
            ks[0] = kv.x; ks[1] = kv.y; ks[2] = kv.z; ks[3] = kv.w;
            vs[0] = vv.x; vs[1] = vv.y; vs[2] = vv.z; vs[3] = vv.w;
        }
        __syncthreads();

        float s[8][4];
#pragma unroll
        for (int i = 0; i < 8; i++)
#pragma unroll
            for (int j = 0; j < 4; j++) s[i][j] = 0.f;

#pragma unroll 2
        for (int d4 = 0; d4 < 16; d4++) {
            float4 kk[4];
#pragma unroll
            for (int j = 0; j < 4; j++)
                kk[j] = *(const float4*)&Ks[(tcol + 16 * j) * SSTR + d4 * 4];
#pragma unroll
            for (int i = 0; i < 8; i++) {
                float4 q = *(const float4*)&Qs[(r0 + i) * SSTR + d4 * 4];
#pragma unroll
                for (int j = 0; j < 4; j++)
                    s[i][j] += q.x * kk[j].x + q.y * kk[j].y +
                               q.z * kk[j].z + q.w * kk[j].w;
            }
        }

#pragma unroll
        for (int i = 0; i < 8; i++) {
            float mt = fmaxf(fmaxf(s[i][0], s[i][1]), fmaxf(s[i][2], s[i][3]));
            mt = fmaxf(mt, __shfl_xor_sync(0xffffffffu, mt, 1));
            mt = fmaxf(mt, __shfl_xor_sync(0xffffffffu, mt, 2));
            mt = fmaxf(mt, __shfl_xor_sync(0xffffffffu, mt, 4));
            mt = fmaxf(mt, __shfl_xor_sync(0xffffffffu, mt, 8));
            float mnew  = fmaxf(m[i], mt);
            float alpha = __expf(m[i] - mnew);
            float ls = 0.f;
#pragma unroll
            for (int j = 0; j < 4; j++) {
                s[i][j] = __expf(s[i][j] - mnew);
                ls += s[i][j];
            }
            ls += __shfl_xor_sync(0xffffffffu, ls, 1);
            ls += __shfl_xor_sync(0xffffffffu, ls, 2);
            ls += __shfl_xor_sync(0xffffffffu, ls, 4);
            ls += __shfl_xor_sync(0xffffffffu, ls, 8);
            l[i] = l[i] * alpha + ls;
            m[i] = mnew;
#pragma unroll
            for (int j = 0; j < 4; j++) o[i][j] *= alpha;
            float* pr = &Ps[(r0 + i) * SSTR + tcol];
#pragma unroll
            for (int j = 0; j < 4; j++) pr[16 * j] = s[i][j];
        }
        __syncthreads();

#pragma unroll 2
        for (int c4 = 0; c4 < 16; c4++) {
            float4 vv[4];
#pragma unroll
            for (int j = 0; j < 4; j++)
                vv[j] = *(const float4*)&Vs[(c4 * 4 + j) * SSTR + d0];
#pragma unroll
            for (int i = 0; i < 8; i++) {
                float4 p = *(const float4*)&Ps[(r0 + i) * SSTR + c4 * 4];
                o[i][0] += p.x * vv[0].x + p.y * vv[1].x + p.z * vv[2].x + p.w * vv[3].x;
                o[i][1] += p.x * vv[0].y + p.y * vv[1].y + p.z * vv[2].y + p.w * vv[3].y;
                o[i][2] += p.x * vv[0].z + p.y * vv[1].z + p.z * vv[2].z + p.w * vv[3].z;
                o[i][3] += p.x * vv[0].w + p.y * vv[1].w + p.z * vv[2].w + p.w * vv[3].w;
            }
        }
    }

#pragma unroll
    for (int i = 0; i < 8; i++) {
        float inv = 1.f / l[i];
        __nv_bfloat16 h0, h1, h2, h3, l0, l1, l2, l3;
        split1(o[i][0] * inv, h0, l0);
        split1(o[i][1] * inv, h1, l1);
        split1(o[i][2] * inv, h2, l2);
        split1(o[i][3] * inv, h3, l3);
        size_t idx = (size_t)b * SEQ * DIM + (size_t)(qt + r0 + i) * DIM
                   + h * HD + d0;
        uint2 hv, lv;
        hv.x = pack2(h0, h1); hv.y = pack2(h2, h3);
        lv.x = pack2(l0, l1); lv.y = pack2(l2, l3);
        *(uint2*)(oh + idx) = hv;
        *(uint2*)(ol + idx) = lv;
    }
}

extern "C" void kernel_launch(void* const* d_in, const int* in_sizes, int n_in,
                              void* d_out, int out_size)
{
    const float* x      = (const float*)d_in[0];
    const float* qkv_w  = (const float*)d_in[1];
    const float* qkv_b  = (const float*)d_in[2];
    const float* proj_w = (const float*)d_in[3];
    const float* proj_b = (const float*)d_in[4];
    float* out = (float*)d_out;

    float* qkv;
    __nv_bfloat16 *xh, *xl, *qwh, *qwl, *pwh, *pwl, *ah, *al;
    cudaGetSymbolAddress((void**)&qkv, g_qkv);
    cudaGetSymbolAddress((void**)&xh,  g_xh);
    cudaGetSymbolAddress((void**)&xl,  g_xl);
    cudaGetSymbolAddress((void**)&qwh, g_qwh);
    cudaGetSymbolAddress((void**)&qwl, g_qwl);
    cudaGetSymbolAddress((void**)&pwh, g_pwh);
    cudaGetSymbolAddress((void**)&pwl, g_pwl);
    cudaGetSymbolAddress((void**)&ah,  g_ah);
    cudaGetSymbolAddress((void**)&al,  g_al);

    const int attn_smem = SSTR * (BR + BC + BC + BR) * sizeof(float);
    cudaFuncSetAttribute(attn_kernel,
                         cudaFuncAttributeMaxDynamicSharedMemorySize, attn_smem);

    // splits
    const int nx = M_TOT * DIM, nqw = QKV_N * DIM, npw = DIM * DIM;
    split_kernel<<<(nx / 4 + 255) / 256, 256>>>(x, xh, xl, nx);
    split_kernel<<<(nqw / 4 + 255) / 256, 256>>>(qkv_w, qwh, qwl, nqw);
    split_kernel<<<(npw / 4 + 255) / 256, 256>>>(proj_w, pwh, pwl, npw);

    // QKV projection: [8192, 2304]
    gemm_bf16x3<<<dim3(QKV_N / 128, M_TOT / 128), 256>>>(
        xh, xl, qwh, qwl, qkv_b, qkv, QKV_N, DIM);

    // Attention -> bf16 hi/lo
    attn_kernel<<<dim3(SEQ / BR, BATCH * NH), 256, attn_smem>>>(qkv, ah, al);

    // Output projection: [8192, 768]
    gemm_bf16x3<<<dim3(DIM / 128, M_TOT / 128), 256>>>(
        ah, al, pwh, pwl, proj_b, out, DIM, DIM);
}

// round 5
// speedup vs baseline: 6.8712x; 1.4722x over previous
#include <cuda_runtime.h>
#include <cuda_bf16.h>
#include <cstdint>

#define DIM   768
#define NH    12
#define HD    64
#define BATCH 8
#define SEQ   1024
#define M_TOT (BATCH * SEQ)   // 8192
#define QKV_N (3 * DIM)       // 2304

// Scratch (no allocation allowed in kernel_launch)
static __device__ float g_qkv[(size_t)M_TOT * QKV_N];          // [8192, 2304] f32
static __device__ __nv_bfloat16 g_xh[(size_t)M_TOT * DIM];     // x hi/lo
static __device__ __nv_bfloat16 g_xl[(size_t)M_TOT * DIM];
static __device__ __nv_bfloat16 g_qwh[(size_t)QKV_N * DIM];    // qkv_w hi/lo
static __device__ __nv_bfloat16 g_qwl[(size_t)QKV_N * DIM];
static __device__ __nv_bfloat16 g_pwh[(size_t)DIM * DIM];      // proj_w hi/lo
static __device__ __nv_bfloat16 g_pwl[(size_t)DIM * DIM];
static __device__ __nv_bfloat16 g_ah[(size_t)M_TOT * DIM];     // attn out hi/lo
static __device__ __nv_bfloat16 g_al[(size_t)M_TOT * DIM];

// ---------------------------------------------------------------------------
// helpers
// ---------------------------------------------------------------------------
__device__ __forceinline__ uint32_t smem_u32(const void* p) {
    uint32_t a;
    asm("{ .reg .u64 t; cvta.to.shared.u64 t, %1; cvt.u32.u64 %0, t; }"
        : "=r"(a) : "l"(p));
    return a;
}
__device__ __forceinline__ void split1(float v, __nv_bfloat16& h, __nv_bfloat16& l) {
    h = __float2bfloat16(v);
    l = __float2bfloat16(v - __bfloat162float(h));
}
__device__ __forceinline__ uint32_t pack2(__nv_bfloat16 a, __nv_bfloat16 b) {
    return (uint32_t)__bfloat16_as_ushort(a) |
           ((uint32_t)__bfloat16_as_ushort(b) << 16);
}
// pack hi parts of two floats / lo parts of two floats
__device__ __forceinline__ void split_pair(float a, float b,
                                           uint32_t& hi, uint32_t& lo) {
    __nv_bfloat16 ha, la, hb, lb;
    split1(a, ha, la); split1(b, hb, lb);
    hi = pack2(ha, hb); lo = pack2(la, lb);
}

#define LDX4(r, addr)                                                        \
    asm volatile("ldmatrix.sync.aligned.m8n8.x4.shared.b16 {%0,%1,%2,%3}, [%4];" \
        : "=r"((r)[0]), "=r"((r)[1]), "=r"((r)[2]), "=r"((r)[3])             \
        : "r"(addr))

#define LDX4T(r, addr)                                                       \
    asm volatile("ldmatrix.sync.aligned.m8n8.x4.trans.shared.b16 {%0,%1,%2,%3}, [%4];" \
        : "=r"((r)[0]), "=r"((r)[1]), "=r"((r)[2]), "=r"((r)[3])             \
        : "r"(addr))

#define MMA_BF16(c, a, b0, b1)                                               \
    asm volatile("mma.sync.aligned.m16n8k16.row.col.f32.bf16.bf16.f32 "      \
        "{%0,%1,%2,%3},{%4,%5,%6,%7},{%8,%9},{%0,%1,%2,%3};"                 \
        : "+f"((c)[0]), "+f"((c)[1]), "+f"((c)[2]), "+f"((c)[3])             \
        : "r"((a)[0]), "r"((a)[1]), "r"((a)[2]), "r"((a)[3]),                \
          "r"(b0), "r"(b1))

// ---------------------------------------------------------------------------
// f32 -> (hi, lo) bf16 split, vectorized by 4
// ---------------------------------------------------------------------------
__global__ void split_kernel(const float* __restrict__ in,
                             __nv_bfloat16* __restrict__ h,
                             __nv_bfloat16* __restrict__ l, int n)
{
    int i = (blockIdx.x * blockDim.x + threadIdx.x) * 4;
    if (i >= n) return;
    float4 v = *(const float4*)(in + i);
    uint32_t h0, l0, h1, l1;
    split_pair(v.x, v.y, h0, l0);
    split_pair(v.z, v.w, h1, l1);
    *(uint2*)(h + i) = make_uint2(h0, h1);
    *(uint2*)(l + i) = make_uint2(l0, l1);
}

// ---------------------------------------------------------------------------
// bf16 3-term GEMM (unchanged from round 4)
// ---------------------------------------------------------------------------
#define SB 40

__global__ __launch_bounds__(256) void gemm_bf16x3(
    const __nv_bfloat16* __restrict__ Ah, const __nv_bfloat16* __restrict__ Al,
    const __nv_bfloat16* __restrict__ Bh, const __nv_bfloat16* __restrict__ Bl,
    const float* __restrict__ bias, float* __restrict__ C, int N, int K)
{
    __shared__ __align__(16) __nv_bfloat16 sAh[128 * SB];
    __shared__ __align__(16) __nv_bfloat16 sAl[128 * SB];
    __shared__ __align__(16) __nv_bfloat16 sBh[128 * SB];
    __shared__ __align__(16) __nv_bfloat16 sBl[128 * SB];

    const int tid  = threadIdx.x;
    const int wid  = tid >> 5;
    const int lane = tid & 31;
    const int wm   = wid & 1;
    const int wn   = wid >> 1;
    const int bm   = blockIdx.y * 128;
    const int bn   = blockIdx.x * 128;

    const uint32_t uAh = smem_u32(sAh), uAl = smem_u32(sAl);
    const uint32_t uBh = smem_u32(sBh), uBl = smem_u32(sBl);

    const uint32_t offA = (uint32_t)(lane & 15) * (SB * 2) + ((lane & 16) ? 16 : 0);
    const uint32_t offB = (uint32_t)(((lane & 16) >> 1) + (lane & 7)) * (SB * 2)
                        + ((lane & 8) ? 16 : 0);

    const int lrow = tid >> 1;
    const int cb   = (tid & 1) * 16;
    const __nv_bfloat16* pAh = Ah + (size_t)(bm + lrow) * K + cb;
    const __nv_bfloat16* pAl = Al + (size_t)(bm + lrow) * K + cb;
    const __nv_bfloat16* pBh = Bh + (size_t)(bn + lrow) * K + cb;
    const __nv_bfloat16* pBl = Bl + (size_t)(bn + lrow) * K + cb;
    __nv_bfloat16* qAh = &sAh[lrow * SB + cb];
    __nv_bfloat16* qAl = &sAl[lrow * SB + cb];
    __nv_bfloat16* qBh = &sBh[lrow * SB + cb];
    __nv_bfloat16* qBl = &sBl[lrow * SB + cb];

    float acc[4][4][4];
#pragma unroll
    for (int t = 0; t < 4; t++)
#pragma unroll
        for (int u = 0; u < 4; u++)
#pragma unroll
            for (int j = 0; j < 4; j++) acc[t][u][j] = 0.f;

    const int nit = K / 32;
    uint4 rah0 = *(const uint4*)(pAh);     uint4 rah1 = *(const uint4*)(pAh + 8);
    uint4 ral0 = *(const uint4*)(pAl);     uint4 ral1 = *(const uint4*)(pAl + 8);
    uint4 rbh0 = *(const uint4*)(pBh);     uint4 rbh1 = *(const uint4*)(pBh + 8);
    uint4 rbl0 = *(const uint4*)(pBl);     uint4 rbl1 = *(const uint4*)(pBl + 8);

    for (int c = 0; c < nit; c++) {
        *(uint4*)(qAh) = rah0; *(uint4*)(qAh + 8) = rah1;
        *(uint4*)(qAl) = ral0; *(uint4*)(qAl + 8) = ral1;
        *(uint4*)(qBh) = rbh0; *(uint4*)(qBh + 8) = rbh1;
        *(uint4*)(qBl) = rbl0; *(uint4*)(qBl + 8) = rbl1;
        __syncthreads();

        if (c + 1 < nit) {
            const int k0 = (c + 1) * 32;
            rah0 = *(const uint4*)(pAh + k0); rah1 = *(const uint4*)(pAh + k0 + 8);
            ral0 = *(const uint4*)(pAl + k0); ral1 = *(const uint4*)(pAl + k0 + 8);
            rbh0 = *(const uint4*)(pBh + k0); rbh1 = *(const uint4*)(pBh + k0 + 8);
            rbl0 = *(const uint4*)(pBl + k0); rbl1 = *(const uint4*)(pBl + k0 + 8);
        }

#pragma unroll
        for (int kk = 0; kk < 32; kk += 16) {
            uint32_t ah[4][4], al[4][4], bh[2][4], bl[2][4];
#pragma unroll
            for (int t = 0; t < 4; t++) {
                uint32_t base = (uint32_t)((wm * 64 + t * 16) * (SB * 2)) + kk * 2;
                LDX4(ah[t], uAh + base + offA);
                LDX4(al[t], uAl + base + offA);
            }
#pragma unroll
            for (int p = 0; p < 2; p++) {
                uint32_t base = (uint32_t)((wn * 32 + p * 16) * (SB * 2)) + kk * 2;
                LDX4(bh[p], uBh + base + offB);
                LDX4(bl[p], uBl + base + offB);
            }
#pragma unroll
            for (int t = 0; t < 4; t++) {
#pragma unroll
                for (int u = 0; u < 4; u++) {
                    const int p = u >> 1, o = (u & 1) * 2;
                    MMA_BF16(acc[t][u], ah[t], bh[p][o], bh[p][o + 1]);
                    MMA_BF16(acc[t][u], ah[t], bl[p][o], bl[p][o + 1]);
                    MMA_BF16(acc[t][u], al[t], bh[p][o], bh[p][o + 1]);
                }
            }
        }
        __syncthreads();
    }

    const int er = lane >> 2;
    const int ec = (lane & 3) * 2;
#pragma unroll
    for (int t = 0; t < 4; t++) {
        const int row = bm + wm * 64 + t * 16 + er;
#pragma unroll
        for (int u = 0; u < 4; u++) {
            const int col = bn + wn * 32 + u * 8 + ec;
            const float b0 = bias[col], b1 = bias[col + 1];
            float2 v0 = {acc[t][u][0] + b0, acc[t][u][1] + b1};
            float2 v1 = {acc[t][u][2] + b0, acc[t][u][3] + b1};
            *(float2*)&C[(size_t)row * N + col]       = v0;
            *(float2*)&C[(size_t)(row + 8) * N + col] = v1;
        }
    }
}

// ---------------------------------------------------------------------------
// Tensor-core flash attention: 3-term bf16 HMMA for QK^T and PV.
// CTA: 64 q-rows x one (b,h); 4 warps, 16 rows each. Bc = 64 keys/tile.
// K/V staged f32->hi/lo bf16 in smem (stride 72 bf16 -> conflict-free ldmatrix).
// Output written as bf16 hi/lo for the proj GEMM.
// ---------------------------------------------------------------------------
#define KSTR 72

__global__ __launch_bounds__(128) void attn_mma(const float* __restrict__ qkv,
                                                __nv_bfloat16* __restrict__ oh,
                                                __nv_bfloat16* __restrict__ ol)
{
    __shared__ __align__(16) __nv_bfloat16 sKh[64 * KSTR];
    __shared__ __align__(16) __nv_bfloat16 sKl[64 * KSTR];
    __shared__ __align__(16) __nv_bfloat16 sVh[64 * KSTR];
    __shared__ __align__(16) __nv_bfloat16 sVl[64 * KSTR];

    const int tid  = threadIdx.x;
    const int w    = tid >> 5;
    const int lane = tid & 31;
    const int qt   = blockIdx.x * 64;
    const int b    = blockIdx.y / NH;
    const int h    = blockIdx.y % NH;

    const float* base = qkv + (size_t)b * SEQ * QKV_N + h * HD;

    const uint32_t uKh = smem_u32(sKh), uKl = smem_u32(sKl);
    const uint32_t uVh = smem_u32(sVh), uVl = smem_u32(sVl);

    const uint32_t offA = (uint32_t)(lane & 15) * (KSTR * 2) + ((lane & 16) ? 16 : 0);
    const uint32_t offB = (uint32_t)(((lane & 16) >> 1) + (lane & 7)) * (KSTR * 2)
                        + ((lane & 8) ? 16 : 0);

    // loader mapping: row = tid/2, 32-col half
    const int lr = tid >> 1;
    const int lc = (tid & 1) * 32;

    // ---- stage Q (scaled, split) into sKh/sKl, pull A-frags to registers ----
    {
        const float* qp = base + (size_t)(qt + lr) * QKV_N + lc;
        __nv_bfloat16* dh = &sKh[lr * KSTR + lc];
        __nv_bfloat16* dl = &sKl[lr * KSTR + lc];
#pragma unroll
        for (int j = 0; j < 8; j++) {
            float4 v = *(const float4*)(qp + j * 4);
            uint32_t h0, l0, h1, l1;
            split_pair(v.x * 0.125f, v.y * 0.125f, h0, l0);
            split_pair(v.z * 0.125f, v.w * 0.125f, h1, l1);
            *(uint2*)(dh + j * 4) = make_uint2(h0, h1);
            *(uint2*)(dl + j * 4) = make_uint2(l0, l1);
        }
    }
    __syncthreads();

    uint32_t qh[4][4], ql[4][4];
#pragma unroll
    for (int ks = 0; ks < 4; ks++) {
        uint32_t a = (uint32_t)(w * 16) * (KSTR * 2) + ks * 32 + offA;
        LDX4(qh[ks], uKh + a);
        LDX4(ql[ks], uKl + a);
    }
    __syncthreads();

    float oacc[8][4];
#pragma unroll
    for (int u = 0; u < 8; u++)
#pragma unroll
        for (int j = 0; j < 4; j++) oacc[u][j] = 0.f;
    float m0 = -1e30f, m1 = -1e30f, l0 = 0.f, l1 = 0.f;

    for (int kt = 0; kt < SEQ / 64; kt++) {
        // ---- load K,V tiles (f32 -> hi/lo bf16) ----
        {
            const float* kp = base + (size_t)(kt * 64 + lr) * QKV_N + DIM + lc;
            __nv_bfloat16* kh = &sKh[lr * KSTR + lc];
            __nv_bfloat16* kl = &sKl[lr * KSTR + lc];
            __nv_bfloat16* vh = &sVh[lr * KSTR + lc];
            __nv_bfloat16* vl = &sVl[lr * KSTR + lc];
#pragma unroll
            for (int j = 0; j < 8; j++) {
                float4 kv = *(const float4*)(kp + j * 4);
                float4 vv = *(const float4*)(kp + DIM + j * 4);
                uint32_t h0, lo0, h1, lo1;
                split_pair(kv.x, kv.y, h0, lo0);
                split_pair(kv.z, kv.w, h1, lo1);
                *(uint2*)(kh + j * 4) = make_uint2(h0, h1);
                *(uint2*)(kl + j * 4) = make_uint2(lo0, lo1);
                split_pair(vv.x, vv.y, h0, lo0);
                split_pair(vv.z, vv.w, h1, lo1);
                *(uint2*)(vh + j * 4) = make_uint2(h0, h1);
                *(uint2*)(vl + j * 4) = make_uint2(lo0, lo1);
            }
        }
        __syncthreads();

        // ---- S = Q @ K^T (3-term) ----
        float sacc[8][4];
#pragma unroll
        for (int u = 0; u < 8; u++)
#pragma unroll
            for (int j = 0; j < 4; j++) sacc[u][j] = 0.f;

#pragma unroll
        for (int ks = 0; ks < 4; ks++) {
#pragma unroll
            for (int np = 0; np < 4; np++) {
                uint32_t kh[4], kl[4];
                uint32_t a = (uint32_t)(np * 16) * (KSTR * 2) + ks * 32 + offB;
                LDX4(kh, uKh + a);
                LDX4(kl, uKl + a);
                const int u = np * 2;
                MMA_BF16(sacc[u],     qh[ks], kh[0], kh[1]);
                MMA_BF16(sacc[u],     qh[ks], kl[0], kl[1]);
                MMA_BF16(sacc[u],     ql[ks], kh[0], kh[1]);
                MMA_BF16(sacc[u + 1], qh[ks], kh[2], kh[3]);
                MMA_BF16(sacc[u + 1], qh[ks], kl[2], kl[3]);
                MMA_BF16(sacc[u + 1], ql[ks], kh[2], kh[3]);
            }
        }

        // ---- online softmax (rows er, er+8; reduce across quad lanes) ----
        float mt0 = -1e30f, mt1 = -1e30f;
#pragma unroll
        for (int u = 0; u < 8; u++) {
            mt0 = fmaxf(mt0, fmaxf(sacc[u][0], sacc[u][1]));
            mt1 = fmaxf(mt1, fmaxf(sacc[u][2], sacc[u][3]));
        }
        mt0 = fmaxf(mt0, __shfl_xor_sync(0xffffffffu, mt0, 1));
        mt0 = fmaxf(mt0, __shfl_xor_sync(0xffffffffu, mt0, 2));
        mt1 = fmaxf(mt1, __shfl_xor_sync(0xffffffffu, mt1, 1));
        mt1 = fmaxf(mt1, __shfl_xor_sync(0xffffffffu, mt1, 2));

        const float mn0 = fmaxf(m0, mt0);
        const float mn1 = fmaxf(m1, mt1);
        const float a0 = __expf(m0 - mn0);
        const float a1 = __expf(m1 - mn1);

        float ls0 = 0.f, ls1 = 0.f;
#pragma unroll
        for (int u = 0; u < 8; u++) {
            sacc[u][0] = __expf(sacc[u][0] - mn0);
            sacc[u][1] = __expf(sacc[u][1] - mn0);
            sacc[u][2] = __expf(sacc[u][2] - mn1);
            sacc[u][3] = __expf(sacc[u][3] - mn1);
            ls0 += sacc[u][0] + sacc[u][1];
            ls1 += sacc[u][2] + sacc[u][3];
        }
        ls0 += __shfl_xor_sync(0xffffffffu, ls0, 1);
        ls0 += __shfl_xor_sync(0xffffffffu, ls0, 2);
        ls1 += __shfl_xor_sync(0xffffffffu, ls1, 1);
        ls1 += __shfl_xor_sync(0xffffffffu, ls1, 2);
        l0 = l0 * a0 + ls0;  m0 = mn0;
        l1 = l1 * a1 + ls1;  m1 = mn1;

#pragma unroll
        for (int u = 0; u < 8; u++) {
            oacc[u][0] *= a0; oacc[u][1] *= a0;
            oacc[u][2] *= a1; oacc[u][3] *= a1;
        }

        // ---- pack P into A-frags (hi/lo) ----
        uint32_t pah[4][4], pal[4][4];
#pragma unroll
        for (int t = 0; t < 4; t++) {
            split_pair(sacc[2 * t][0],     sacc[2 * t][1],     pah[t][0], pal[t][0]);
            split_pair(sacc[2 * t][2],     sacc[2 * t][3],     pah[t][1], pal[t][1]);
            split_pair(sacc[2 * t + 1][0], sacc[2 * t + 1][1], pah[t][2], pal[t][2]);
            split_pair(sacc[2 * t + 1][2], sacc[2 * t + 1][3], pah[t][3], pal[t][3]);
        }

        // ---- O += P @ V (3-term; V via ldmatrix.trans) ----
#pragma unroll
        for (int t = 0; t < 4; t++) {
#pragma unroll
            for (int nd = 0; nd < 4; nd++) {
                uint32_t vh[4], vl[4];
                uint32_t a = (uint32_t)(t * 16) * (KSTR * 2) + nd * 32 + offB;
                LDX4T(vh, uVh + a);
                LDX4T(vl, uVl + a);
                const int u = nd * 2;
                MMA_BF16(oacc[u],     pah[t], vh[0], vh[2]);
                MMA_BF16(oacc[u],     pah[t], vl[0], vl[2]);
                MMA_BF16(oacc[u],     pal[t], vh[0], vh[2]);
                MMA_BF16(oacc[u + 1], pah[t], vh[1], vh[3]);
                MMA_BF16(oacc[u + 1], pah[t], vl[1], vl[3]);
                MMA_BF16(oacc[u + 1], pal[t], vh[1], vh[3]);
            }
        }
        __syncthreads();
    }

    // ---- epilogue: O / l -> bf16 hi/lo ----
    const float inv0 = 1.f / l0;
    const float inv1 = 1.f / l1;
    const int er = lane >> 2;
    const int ec = (lane & 3) * 2;
    const size_t tok0 = (size_t)b * SEQ + qt + w * 16 + er;
    const int colb = h * HD + ec;
#pragma unroll
    for (int u = 0; u < 8; u++) {
        const int col = colb + u * 8;
        uint32_t hp, lp;
        split_pair(oacc[u][0] * inv0, oacc[u][1] * inv0, hp, lp);
        *(uint32_t*)(oh + tok0 * DIM + col) = hp;
        *(uint32_t*)(ol + tok0 * DIM + col) = lp;
        split_pair(oacc[u][2] * inv1, oacc[u][3] * inv1, hp, lp);
        *(uint32_t*)(oh + (tok0 + 8) * DIM + col) = hp;
        *(uint32_t*)(ol + (tok0 + 8) * DIM + col) = lp;
    }
}

extern "C" void kernel_launch(void* const* d_in, const int* in_sizes, int n_in,
                              void* d_out, int out_size)
{
    const float* x      = (const float*)d_in[0];
    const float* qkv_w  = (const float*)d_in[1];
    const float* qkv_b  = (const float*)d_in[2];
    const float* proj_w = (const float*)d_in[3];
    const float* proj_b = (const float*)d_in[4];
    float* out = (float*)d_out;

    float* qkv;
    __nv_bfloat16 *xh, *xl, *qwh, *qwl, *pwh, *pwl, *ah, *al;
    cudaGetSymbolAddress((void**)&qkv, g_qkv);
    cudaGetSymbolAddress((void**)&xh,  g_xh);
    cudaGetSymbolAddress((void**)&xl,  g_xl);
    cudaGetSymbolAddress((void**)&qwh, g_qwh);
    cudaGetSymbolAddress((void**)&qwl, g_qwl);
    cudaGetSymbolAddress((void**)&pwh, g_pwh);
    cudaGetSymbolAddress((void**)&pwl, g_pwl);
    cudaGetSymbolAddress((void**)&ah,  g_ah);
    cudaGetSymbolAddress((void**)&al,  g_al);

    // splits
    const int nx = M_TOT * DIM, nqw = QKV_N * DIM, npw = DIM * DIM;
    split_kernel<<<(nx / 4 + 255) / 256, 256>>>(x, xh, xl, nx);
    split_kernel<<<(nqw / 4 + 255) / 256, 256>>>(qkv_w, qwh, qwl, nqw);
    split_kernel<<<(npw / 4 + 255) / 256, 256>>>(proj_w, pwh, pwl, npw);

    // QKV projection: [8192, 2304]
    gemm_bf16x3<<<dim3(QKV_N / 128, M_TOT / 128), 256>>>(
        xh, xl, qwh, qwl, qkv_b, qkv, QKV_N, DIM);

    // Attention (tensor-core) -> bf16 hi/lo
    attn_mma<<<dim3(SEQ / 64, BATCH * NH), 128>>>(qkv, ah, al);

    // Output projection: [8192, 768]
    gemm_bf16x3<<<dim3(DIM / 128, M_TOT / 128), 256>>>(
        ah, al, pwh, pwl, proj_b, out, DIM, DIM);
}